// round 16
// baseline (speedup 1.0000x reference)
#include <cuda_runtime.h>
#include <cstdint>

constexpr int Bc=4, Nn=2048, Dd=256, Hh=4;
constexpr int TJ=32, NT=Nn/TJ;

__device__ float    g_WhR [Bc*Nn*Dd];        // tf32-rounded Wh (B operand)
__device__ float    g_Wa  [8*256];           // [v][k]: v=0..3 src-h, 4..7 dst-h
__device__ float2   g_pq  [Bc*Hh*Nn];        // (exp(es), exp(.2es)) per row
__device__ float2   g_uv  [Bc*Hh*Nn];        // (exp(ed), exp(.2ed)) per col
__device__ float    g_alpha_s[Bc*Hh*Nn*Nn];  // fallback alpha buffer

__device__ __forceinline__ float totf(float x){
    uint32_t u; asm("cvt.rna.tf32.f32 %0, %1;" : "=r"(u) : "f"(x));
    return __uint_as_float(u);
}
__device__ __forceinline__ void mma8(float* d, float4 a, float2 b){
    asm volatile("mma.sync.aligned.m16n8k8.row.col.f32.tf32.tf32.f32 "
        "{%0,%1,%2,%3}, {%4,%5,%6,%7}, {%8,%9}, {%0,%1,%2,%3};"
        : "+f"(d[0]), "+f"(d[1]), "+f"(d[2]), "+f"(d[3])
        : "r"(__float_as_uint(a.x)), "r"(__float_as_uint(a.y)),
          "r"(__float_as_uint(a.z)), "r"(__float_as_uint(a.w)),
          "r"(__float_as_uint(b.x)), "r"(__float_as_uint(b.y)));
}
__device__ __forceinline__ void cpasync16(void* smem_p, const void* gmem){
    unsigned s = (unsigned)__cvta_generic_to_shared(smem_p);
    asm volatile("cp.async.cg.shared.global [%0], [%1], 16;" :: "r"(s), "l"(gmem));
}
#define CP_COMMIT() asm volatile("cp.async.commit_group;")
__device__ __forceinline__ void cp_wait_tail(int rem){
    if(rem>=2)      asm volatile("cp.async.wait_group 2;");
    else if(rem==1) asm volatile("cp.async.wait_group 1;");
    else            asm volatile("cp.async.wait_group 0;");
}

constexpr int AST=36, BST=72;
constexpr int ABUF=128*AST, BBUF=32*BST;
constexpr int STG = ABUF + BBUF;
constexpr int SMEM_PIPE4 = 4*STG*4;          // k1: 110592 B

// mega smem layout (floats)
constexpr int BSTW  = 264;                   // B row stride
constexpr int BTILE = 32*BSTW;               // 8448
constexpr int UVT   = 256;                   // uv tile (4h x 32j x float2)
constexpr int STGM  = BTILE + UVT;           // 8704 per stage
constexpr int SW_OFF= 2*STGM;                // packed words [i][t]: 2048
constexpr int PP_OFF= SW_OFF + 2048;
constexpr int QQ_OFF= PP_OFF + 128;
constexpr int IV_OFF= QQ_OFF + 128;
constexpr int SP_OFF= IV_OFF + 128;
constexpr int SQ_OFF= SP_OFF + 128;
constexpr int SMEM_M= (SQ_OFF + 128)*4;      // 80384 B -> 2 CTA/SM

// ---------------------------------------------------------------------------
// K0: Wa[v][k] = sum_d W[k][h*64+d]*a[h][d]  (v<4: a_src; v>=4: a_dst)
// ---------------------------------------------------------------------------
__global__ void gat_wa(const float* __restrict__ W,
                       const float* __restrict__ a_src,
                       const float* __restrict__ a_dst){
    __shared__ float sa[512];
    const int tid=threadIdx.x;
    sa[tid] = a_src[tid];
    sa[256+tid] = a_dst[tid];
    __syncthreads();
    const float* wrow = W + (size_t)tid*256;
#pragma unroll
    for(int v=0;v<8;v++){
        int h = v&3;
        const float* av = sa + (v>>2)*256 + h*64;
        float s=0.f;
#pragma unroll 16
        for(int d=0;d<64;d++) s += wrow[h*64+d]*av[d];
        g_Wa[v*256+tid]=s;
    }
}

// ---------------------------------------------------------------------------
// K2: proj from h directly: es=h.(W a_src), ed=h.(W a_dst). Warp per (b,n).
// ---------------------------------------------------------------------------
__global__ __launch_bounds__(256)
void gat_proj(const float* __restrict__ hin){
    __shared__ float wa[2048];
    const int tid=threadIdx.x;
#pragma unroll
    for(int k=0;k<8;k++) wa[tid+k*256]=g_Wa[tid+k*256];
    __syncthreads();
    const int row = blockIdx.x*8 + (tid>>5);
    const int lane = tid&31;
    const float* hr = hin + (size_t)row*256 + lane*8;
    float4 x0=*(const float4*)hr, x1=*(const float4*)(hr+4);
    float xs[8]={x0.x,x0.y,x0.z,x0.w,x1.x,x1.y,x1.z,x1.w};
    float dots[8];
#pragma unroll
    for(int v=0;v<8;v++){
        const float* w = wa + v*256 + lane*8;
        dots[v] = xs[0]*w[0]+xs[1]*w[1]+xs[2]*w[2]+xs[3]*w[3]
                + xs[4]*w[4]+xs[5]*w[5]+xs[6]*w[6]+xs[7]*w[7];
    }
#pragma unroll
    for(int v=0;v<8;v++)
#pragma unroll
        for(int o=16;o;o>>=1) dots[v]+=__shfl_xor_sync(0xffffffffu,dots[v],o);
    const int b=row>>11, n=row&2047;
    if(lane<4)
        g_pq[(b*4+lane)*Nn+n]=make_float2(__expf(dots[lane]),__expf(0.2f*dots[lane]));
    else if(lane<8)
        g_uv[(b*4+(lane-4))*Nn+n]=make_float2(__expf(dots[lane]),__expf(0.2f*dots[lane]));
}

// ---------------------------------------------------------------------------
// K1: WhR = tf32(h @ W) via 3-term tf32-split HMMA (fp32-accurate pre-round).
// ---------------------------------------------------------------------------
__global__ __launch_bounds__(256,2)
void gemm_h_w(const float* __restrict__ A, const float* __restrict__ Bw){
    extern __shared__ float sm[];
    const int tid = threadIdx.x, lane = tid & 31;
    const int i0 = blockIdx.x * 128;
    const int n0 = blockIdx.y * 64;
    const int NT_K = 8;
    const int mq = (tid>>5)&3, nq = tid>>7;

    float acc[2][4][4];
#pragma unroll
    for(int mf=0;mf<2;mf++)
#pragma unroll
        for(int nf=0;nf<4;nf++)
#pragma unroll
            for(int q=0;q<4;q++) acc[mf][nf][q]=0.f;

    const int a_row = tid>>3, a_ch = tid&7;
    const int b_j   = tid>>4, b_ch = tid&15;

    auto stage = [&](int t){
        const int j0 = t*TJ;
        float* Asm = sm + (t&3)*STG;
        float* Bsm = Asm + ABUF;
#pragma unroll
        for(int k=0;k<4;k++){
            int row = a_row + k*32;
            cpasync16(Asm + row*AST + a_ch*4,
                      A + (size_t)(i0+row)*256 + j0 + a_ch*4);
        }
#pragma unroll
        for(int k=0;k<2;k++){
            int j = b_j + k*16;
            cpasync16(Bsm + j*BST + b_ch*4,
                      Bw + (size_t)(j0+j)*256 + n0 + b_ch*4);
        }
        CP_COMMIT();
    };

    stage(0); stage(1); stage(2);

    for(int t=0;t<NT_K;t++){
        cp_wait_tail(NT_K-1-t);
        __syncthreads();
        if(t+3 < NT_K) stage(t+3);
        const float* As = sm + (t&3)*STG;
        const float* Bs = As + ABUF;
#pragma unroll
        for(int kb=0;kb<4;kb++){
            float4 avb[2], avs[2];
#pragma unroll
            for(int mf=0;mf<2;mf++){
                int r = mq*32 + mf*16 + (lane>>2);
                int c = kb*8 + (lane&3);
                float4 av = make_float4(As[r*AST + c],     As[(r+8)*AST + c],
                                        As[r*AST + c + 4], As[(r+8)*AST + c + 4]);
                avb[mf] = make_float4(totf(av.x), totf(av.y), totf(av.z), totf(av.w));
                avs[mf] = make_float4(av.x-avb[mf].x, av.y-avb[mf].y,
                                      av.z-avb[mf].z, av.w-avb[mf].w);
            }
#pragma unroll
            for(int nf=0;nf<4;nf++){
                int bj = (kb*8 + (lane&3))*BST + nq*32 + nf*8 + (lane>>2);
                float2 bv = make_float2(Bs[bj], Bs[bj + 4*BST]);
                float2 bvb = make_float2(totf(bv.x), totf(bv.y));
                float2 bvs = make_float2(bv.x-bvb.x, bv.y-bvb.y);
#pragma unroll
                for(int mf=0;mf<2;mf++){
                    mma8(acc[mf][nf], avb[mf], bvb);
                    mma8(acc[mf][nf], avb[mf], bvs);
                    mma8(acc[mf][nf], avs[mf], bvb);
                }
            }
        }
    }

    const int r0 = i0 + mq*32, c0 = n0 + nq*32;
#pragma unroll
    for(int mf=0;mf<2;mf++){
        int row = r0 + mf*16 + (lane>>2);
        size_t o0 = (size_t)row*256 + c0 + (lane&3)*2;
        size_t o1 = o0 + (size_t)8*256;
#pragma unroll
        for(int nf=0;nf<4;nf++){
            *(float2*)(g_WhR + o0 + nf*8) =
                make_float2(totf(acc[mf][nf][0]), totf(acc[mf][nf][1]));
            *(float2*)(g_WhR + o1 + nf*8) =
                make_float2(totf(acc[mf][nf][2]), totf(acc[mf][nf][3]));
        }
    }
}

// ---------------------------------------------------------------------------
// K3 (mega): per block (b, 32 rows):
//   phase 1: read own adj rows -> packed bit-words (smem) + iv (MUFU-free sums)
//   phase 2: 64 j-tiles: stage WhR+uv (cp.async x2 buf), recompute alpha in
//            regs for HMMA A-frags, write alpha tile to gmem, MMA N=256.
// ---------------------------------------------------------------------------
__global__ __launch_bounds__(256,2)
void gat_mega(const int* __restrict__ adj, float* __restrict__ h_out,
              float* __restrict__ alpha_out){
    extern __shared__ float sm[];
    uint32_t* sw = (uint32_t*)(sm + SW_OFF);
    float* PP = sm + PP_OFF;
    float* QQ = sm + QQ_OFF;
    float* ivs= sm + IV_OFF;
    float* sp = sm + SP_OFF;
    float* sq = sm + SQ_OFF;
    const int tid=threadIdx.x, lane=tid&31, wid=tid>>5;
    const int b  = blockIdx.x >> 6;
    const int i0 = (blockIdx.x & 63) * 32;

    auto stage=[&](int t){
        float* S = sm + (t&1)*STGM;
        const int j = tid>>3, ch = tid&7;
        const float* wsrc = g_WhR + ((size_t)(b*Nn) + t*32 + j)*Dd;
#pragma unroll
        for(int k=0;k<8;k++)
            cpasync16(S + j*BSTW + (ch+8*k)*4, wsrc + (ch+8*k)*4);
        if(tid<64){
            int hh=tid>>4, jq=tid&15;
            cpasync16(S + BTILE + (hh*32 + jq*2)*2,
                      (const float*)(g_uv + (size_t)(b*4+hh)*Nn + t*32 + jq*2));
        }
        CP_COMMIT();
    };

    stage(0); stage(1);   // B/uv independent of phase 1 — overlap with it

    if(tid<128){
        float2 pq = g_pq[(b*4+(tid>>5))*Nn + i0 + (tid&31)];
        sp[tid]=pq.x; sq[tid]=pq.y;
    }
    __syncthreads();

    // ---- phase 1: bits + iv ----
    {
        const int i = tid>>3, g = tid&7;
        const int* arow = adj + ((size_t)(b*Nn + i0 + i))*Nn + g*4;
        float P[4]={sp[i],sp[32+i],sp[64+i],sp[96+i]};
        float Q[4]={sq[i],sq[32+i],sq[64+i],sq[96+i]};
        float S4[4]={0.f,0.f,0.f,0.f};
#pragma unroll 2
        for(int q=0;q<64;q++){
            int4 a = *(const int4*)(arow + q*32);
            int m[4] = {a.x,a.y,a.z,a.w};
            const int j0 = g*4 + q*32;
#pragma unroll
            for(int h=0;h<4;h++){
                const float* up = (const float*)(g_uv + (size_t)(b*4+h)*Nn) + 2*j0;
                float4 x0 = *(const float4*)up;
                float4 x1 = *(const float4*)(up+4);
                float e0 = fmaxf(P[h]*x0.x, Q[h]*x0.y);
                float e1 = fmaxf(P[h]*x0.z, Q[h]*x0.w);
                float e2 = fmaxf(P[h]*x1.x, Q[h]*x1.y);
                float e3 = fmaxf(P[h]*x1.z, Q[h]*x1.w);
                if(m[0]) S4[h]+=e0;
                if(m[1]) S4[h]+=e1;
                if(m[2]) S4[h]+=e2;
                if(m[3]) S4[h]+=e3;
            }
            uint32_t word = ((m[0]?1u:0u)|(m[1]?2u:0u)|(m[2]?4u:0u)|(m[3]?8u:0u)) << (g*4);
            word |= __shfl_xor_sync(0xffffffffu, word, 1);
            word |= __shfl_xor_sync(0xffffffffu, word, 2);
            word |= __shfl_xor_sync(0xffffffffu, word, 4);
            if(g==0) sw[i*64+q] = word;
        }
#pragma unroll
        for(int h=0;h<4;h++)
#pragma unroll
            for(int o=1;o<8;o<<=1)
                S4[h] += __shfl_xor_sync(0xffffffffu, S4[h], o);
        if(g==0)
#pragma unroll
            for(int h=0;h<4;h++)
                ivs[h*32+i] = (S4[h]>0.f) ? (1.f/S4[h]) : 0.f;
    }
    __syncthreads();
    if(tid<128){ float v=ivs[tid]; PP[tid]=sp[tid]*v; QQ[tid]=sq[tid]*v; }
    __syncthreads();

    // ---- phase 2 ----
    const int mq = wid&1, nq = wid>>1, h = nq;
    const int r_lo = lane>>2;
    const int ia = mq*16 + r_lo;
    const float P0=PP[h*32+ia],   Q0=QQ[h*32+ia];
    const float P1=PP[h*32+ia+8], Q1=QQ[h*32+ia+8];
    // writer mapping
    const int wh = tid>>6, ig = (tid>>3)&7, jq = tid&7;
    const float Pw[4] = {PP[wh*32+ig], PP[wh*32+ig+8], PP[wh*32+ig+16], PP[wh*32+ig+24]};
    const float Qw[4] = {QQ[wh*32+ig], QQ[wh*32+ig+8], QQ[wh*32+ig+16], QQ[wh*32+ig+24]};
    float* abw = alpha_out + ((size_t)((b*4+wh)*Nn) + i0)*Nn + jq*4;

    float acc[8][4];
#pragma unroll
    for(int nf=0;nf<8;nf++)
#pragma unroll
        for(int q=0;q<4;q++) acc[nf][q]=0.f;

    for(int t=0;t<NT;t++){
        cp_wait_tail((t+1<NT)?1:0);
        __syncthreads();
        const float* S = sm + (t&1)*STGM;
        const float2* uvt = (const float2*)(S + BTILE);
        // gemm
        const uint32_t b0 = sw[ia*64+t], b1 = sw[(ia+8)*64+t];
#pragma unroll
        for(int kb=0;kb<4;kb++){
            const int c0 = kb*8 + (lane&3);
            float2 x0 = uvt[h*32 + c0];
            float2 x1 = uvt[h*32 + c0 + 4];
            float ax = ((b0>>c0)&1u)     ? fmaxf(P0*x0.x, Q0*x0.y) : 0.f;
            float ay = ((b1>>c0)&1u)     ? fmaxf(P1*x0.x, Q1*x0.y) : 0.f;
            float az = ((b0>>(c0+4))&1u) ? fmaxf(P0*x1.x, Q0*x1.y) : 0.f;
            float aw = ((b1>>(c0+4))&1u) ? fmaxf(P1*x1.x, Q1*x1.y) : 0.f;
            float4 av = make_float4(ax,ay,az,aw);
#pragma unroll
            for(int nf=0;nf<8;nf++){
                int n = nq*64 + nf*8 + (lane>>2);
                float2 bv = make_float2(S[c0*BSTW + n], S[(c0+4)*BSTW + n]);
                mma8(acc[nf], av, bv);
            }
        }
        // writer: alpha tile (4h x 32i x 32j) to gmem
        {
            const float2* uvw = uvt + wh*32 + jq*4;
            float2 y0=uvw[0], y1=uvw[1], y2=uvw[2], y3=uvw[3];
#pragma unroll
            for(int r=0;r<4;r++){
                int i = ig + r*8;
                uint32_t nib = sw[i*64+t] >> (jq*4);
                float4 o;
                o.x = (nib&1u) ? fmaxf(Pw[r]*y0.x, Qw[r]*y0.y) : 0.f;
                o.y = (nib&2u) ? fmaxf(Pw[r]*y1.x, Qw[r]*y1.y) : 0.f;
                o.z = (nib&4u) ? fmaxf(Pw[r]*y2.x, Qw[r]*y2.y) : 0.f;
                o.w = (nib&8u) ? fmaxf(Pw[r]*y3.x, Qw[r]*y3.y) : 0.f;
                *(float4*)(abw + (size_t)i*Nn + t*32) = o;
            }
        }
        __syncthreads();
        if(t+2<NT) stage(t+2);
    }

    // epilogue h_out
    const int row = i0 + mq*16 + r_lo;
    float* p0 = h_out + ((size_t)(b*Nn)+row)*Dd + nq*64 + (lane&3)*2;
    float* p1 = p0 + (size_t)8*Dd;
#pragma unroll
    for(int nf=0;nf<8;nf++){
        *(float2*)(p0+nf*8) = make_float2(acc[nf][0],acc[nf][1]);
        *(float2*)(p1+nf*8) = make_float2(acc[nf][2],acc[nf][3]);
    }
}

// ---------------------------------------------------------------------------
extern "C" void kernel_launch(void* const* d_in, const int* in_sizes, int n_in,
                              void* d_out, int out_size){
    const float* h     = (const float*)d_in[0];
    const int*   adj   = (const int*)d_in[1];
    const float* W     = (const float*)d_in[2];
    const float* a_src = (const float*)d_in[3];
    const float* a_dst = (const float*)d_in[4];
    float* out = (float*)d_out;

    const long long houtN  = (long long)Bc*Nn*Dd;
    const long long alphaN = (long long)Bc*Hh*Nn*Nn;
    bool has_alpha = ((long long)out_size >= houtN + alphaN);
    float* alpha_buf;
    if(has_alpha){
        alpha_buf = out + houtN;
    } else {
        cudaGetSymbolAddress((void**)&alpha_buf, g_alpha_s);
    }

    cudaFuncSetAttribute(gemm_h_w, cudaFuncAttributeMaxDynamicSharedMemorySize,
                         SMEM_PIPE4);
    cudaFuncSetAttribute(gat_mega, cudaFuncAttributeMaxDynamicSharedMemorySize,
                         SMEM_M);

    gat_wa<<<1,256>>>(W, a_src, a_dst);
    gat_proj<<<(Bc*Nn)/8,256>>>(h);
    gemm_h_w<<<dim3(64,4),256,SMEM_PIPE4>>>(h, W);
    gat_mega<<<Bc*64,256,SMEM_M>>>(adj, out, alpha_buf);
}

// round 17
// speedup vs baseline: 1.9629x; 1.9629x over previous
#include <cuda_runtime.h>
#include <cstdint>

constexpr int Bc=4, Nn=2048, Dd=256, Hh=4;
constexpr int TJ=32, NT=Nn/TJ;

__device__ float    g_WhR [Bc*Nn*Dd];        // tf32-rounded Wh (B operand)
__device__ float    g_Wa  [8*256];           // [v][k]: v<4 src-h, v>=4 dst-h
__device__ float2   g_pq  [Bc*Hh*Nn];        // (exp(es), exp(.2es)) per row
__device__ float2   g_uv  [Bc*Hh*Nn];        // (exp(ed), exp(.2ed)) per col
__device__ float    g_ivs [Bc*Hh*Nn];        // 1/rowsum
__device__ uint32_t g_bits[Bc*64*Nn];        // [b][w=j/32][i]
__device__ float    g_alpha_s[Bc*Hh*Nn*Nn]; // fallback alpha buffer

__device__ __forceinline__ float totf(float x){
    uint32_t u; asm("cvt.rna.tf32.f32 %0, %1;" : "=r"(u) : "f"(x));
    return __uint_as_float(u);
}
__device__ __forceinline__ void mma8(float* d, float4 a, float2 b){
    asm volatile("mma.sync.aligned.m16n8k8.row.col.f32.tf32.tf32.f32 "
        "{%0,%1,%2,%3}, {%4,%5,%6,%7}, {%8,%9}, {%0,%1,%2,%3};"
        : "+f"(d[0]), "+f"(d[1]), "+f"(d[2]), "+f"(d[3])
        : "r"(__float_as_uint(a.x)), "r"(__float_as_uint(a.y)),
          "r"(__float_as_uint(a.z)), "r"(__float_as_uint(a.w)),
          "r"(__float_as_uint(b.x)), "r"(__float_as_uint(b.y)));
}
__device__ __forceinline__ void cpasync16(void* smem_p, const void* gmem){
    unsigned s = (unsigned)__cvta_generic_to_shared(smem_p);
    asm volatile("cp.async.cg.shared.global [%0], [%1], 16;" :: "r"(s), "l"(gmem));
}
#define CP_COMMIT() asm volatile("cp.async.commit_group;")
__device__ __forceinline__ void cp_wait_tail(int rem){
    if(rem>=2)      asm volatile("cp.async.wait_group 2;");
    else if(rem==1) asm volatile("cp.async.wait_group 1;");
    else            asm volatile("cp.async.wait_group 0;");
}

constexpr int AST=36, BST=72;
constexpr int ABUF=128*AST, BBUF=32*BST;
constexpr int STG = ABUF + BBUF;
constexpr int SMEM_A2 = 2*STG*4;             // fatA: 55296 B (2-stage k1)

// fused gemm stage: B 32x72 + uv 64 + bits 64 (floats)
constexpr int UV_OFF  = 32*BST;              // 2304
constexpr int BIT_OFF = UV_OFF + 64;         // 2368
constexpr int STG3F   = BIT_OFF + 64;        // 2432 floats
constexpr int SMEM_G  = 4*STG3F*4;           // 38912 B -> 5 CTA/SM

// ---------------------------------------------------------------------------
// K0: Wa[v][k] = sum_d W[k][h*64+d]*a[h][d]
// ---------------------------------------------------------------------------
__global__ void gat_wa(const float* __restrict__ W,
                       const float* __restrict__ a_src,
                       const float* __restrict__ a_dst){
    __shared__ float sa[512];
    const int tid=threadIdx.x;
    sa[tid] = a_src[tid];
    sa[256+tid] = a_dst[tid];
    __syncthreads();
    const float* wrow = W + (size_t)tid*256;
#pragma unroll
    for(int v=0;v<8;v++){
        int h = v&3;
        const float* av = sa + (v>>2)*256 + h*64;
        float s=0.f;
#pragma unroll 16
        for(int d=0;d<64;d++) s += wrow[h*64+d]*av[d];
        g_Wa[v*256+tid]=s;
    }
}

// ---------------------------------------------------------------------------
// K2: proj from h directly: dots with 8 Wa vectors; warp per (b,n).
// ---------------------------------------------------------------------------
__global__ __launch_bounds__(256)
void gat_proj(const float* __restrict__ hin){
    __shared__ float wa[2048];
    const int tid=threadIdx.x;
#pragma unroll
    for(int k=0;k<8;k++) wa[tid+k*256]=g_Wa[tid+k*256];
    __syncthreads();
    const int row = blockIdx.x*8 + (tid>>5);
    const int lane = tid&31;
    const float* hr = hin + (size_t)row*256 + lane*8;
    float4 x0=*(const float4*)hr, x1=*(const float4*)(hr+4);
    float xs[8]={x0.x,x0.y,x0.z,x0.w,x1.x,x1.y,x1.z,x1.w};
    float dots[8];
#pragma unroll
    for(int v=0;v<8;v++){
        const float* w = wa + v*256 + lane*8;
        dots[v] = xs[0]*w[0]+xs[1]*w[1]+xs[2]*w[2]+xs[3]*w[3]
                + xs[4]*w[4]+xs[5]*w[5]+xs[6]*w[6]+xs[7]*w[7];
    }
#pragma unroll
    for(int v=0;v<8;v++)
#pragma unroll
        for(int o=16;o;o>>=1) dots[v]+=__shfl_xor_sync(0xffffffffu,dots[v],o);
    const int b=row>>11, n=row&2047;
    if(lane<4)
        g_pq[(b*4+lane)*Nn+n]=make_float2(__expf(dots[lane]),__expf(0.2f*dots[lane]));
    else if(lane<8)
        g_uv[(b*4+(lane-4))*Nn+n]=make_float2(__expf(dots[lane]),__expf(0.2f*dots[lane]));
}

// ---------------------------------------------------------------------------
// fatA: bid<1024 -> stats block (adj -> bits + iv);
//       bid>=1024 -> Wh GEMM tile (3-term tf32 split, 2-stage pipe -> WhR).
// ---------------------------------------------------------------------------
__global__ __launch_bounds__(256,2)
void gat_fatA(const int* __restrict__ adj,
              const float* __restrict__ A, const float* __restrict__ Bw){
    extern __shared__ float sm[];
    const int tid = threadIdx.x, lane = tid & 31;
    const int bid = blockIdx.x;

    if(bid < 1024){
        // ============== stats path (R15-verified) ==============
        __shared__ uint8_t bits[8*512];
        __shared__ float sp[32], sq[32];
        const int b  = bid >> 8;
        const int i0 = (bid & 255) * 8;

        if(tid<32){
            float2 pq = g_pq[(b*Hh + (tid>>3))*Nn + i0 + (tid&7)];
            sp[tid]=pq.x; sq[tid]=pq.y;
        }
        __syncthreads();
        {
            const int i = tid>>5, g = tid&31;
            const int* arow = adj + ((size_t)(b*Nn + i0 + i))*Nn + g*4;
            float P[4]={sp[i],sp[8+i],sp[16+i],sp[24+i]};
            float Q[4]={sq[i],sq[8+i],sq[16+i],sq[24+i]};
            float S[4]={0.f,0.f,0.f,0.f};
#pragma unroll 2
            for(int q=0;q<16;q++){
                int4 a = *(const int4*)(arow + q*128);
                int m[4] = {a.x,a.y,a.z,a.w};
                const int j0 = g*4 + q*128;
#pragma unroll
                for(int h=0;h<4;h++){
                    const float* up = (const float*)(g_uv + (size_t)(b*Hh+h)*Nn + j0);
                    float4 x0 = *(const float4*)up;
                    float4 x1 = *(const float4*)(up+4);
                    float e0 = fmaxf(P[h]*x0.x, Q[h]*x0.y);
                    float e1 = fmaxf(P[h]*x0.z, Q[h]*x0.w);
                    float e2 = fmaxf(P[h]*x1.x, Q[h]*x1.y);
                    float e3 = fmaxf(P[h]*x1.z, Q[h]*x1.w);
                    if(m[0]) S[h]+=e0;
                    if(m[1]) S[h]+=e1;
                    if(m[2]) S[h]+=e2;
                    if(m[3]) S[h]+=e3;
                }
                bits[i*512 + q*32 + g] =
                    (uint8_t)((m[0]?1u:0u)|(m[1]?2u:0u)|(m[2]?4u:0u)|(m[3]?8u:0u));
            }
#pragma unroll
            for(int h=0;h<4;h++)
#pragma unroll
                for(int o=16;o;o>>=1)
                    S[h] += __shfl_xor_sync(0xffffffffu, S[h], o);
            if(g==0)
#pragma unroll
                for(int h=0;h<4;h++)
                    g_ivs[(b*Hh+h)*Nn + i0 + i] = (S[h]>0.f) ? (1.f/S[h]) : 0.f;
        }
        __syncthreads();
#pragma unroll
        for(int k=0;k<2;k++){
            int item = tid + k*256;
            int i = item & 7, w = item >> 3;
            int base = i*512 + w*8;
            uint32_t u0 = *(const uint32_t*)&bits[base];
            uint32_t u1 = *(const uint32_t*)&bits[base+4];
            uint32_t x0 = u0 & 0x0F0F0F0Fu, x1 = u1 & 0x0F0F0F0Fu;
            x0 = (x0 | (x0>>4)) & 0x00FF00FFu; x0 = (x0 | (x0>>8)) & 0xFFFFu;
            x1 = (x1 | (x1>>4)) & 0x00FF00FFu; x1 = (x1 | (x1>>8)) & 0xFFFFu;
            g_bits[((size_t)b*64 + w)*Nn + i0 + i] = x0 | (x1<<16);
        }
        return;
    }

    // ============== k1 path: Wh tile -> WhR (2-stage) ==============
    const int kb = bid - 1024;
    const int i0 = (kb & 63) * 128;
    const int n0 = (kb >> 6) * 64;
    const int NT_K = 8;
    const int mq = (tid>>5)&3, nq = tid>>7;

    float acc[2][4][4];
#pragma unroll
    for(int mf=0;mf<2;mf++)
#pragma unroll
        for(int nf=0;nf<4;nf++)
#pragma unroll
            for(int q=0;q<4;q++) acc[mf][nf][q]=0.f;

    const int a_row = tid>>3, a_ch = tid&7;
    const int b_j   = tid>>4, b_ch = tid&15;

    auto stage = [&](int t){
        const int j0 = t*TJ;
        float* Asm = sm + (t&1)*STG;
        float* Bsm = Asm + ABUF;
#pragma unroll
        for(int k=0;k<4;k++){
            int row = a_row + k*32;
            cpasync16(Asm + row*AST + a_ch*4,
                      A + (size_t)(i0+row)*256 + j0 + a_ch*4);
        }
#pragma unroll
        for(int k=0;k<2;k++){
            int j = b_j + k*16;
            cpasync16(Bsm + j*BST + b_ch*4,
                      Bw + (size_t)(j0+j)*256 + n0 + b_ch*4);
        }
        CP_COMMIT();
    };

    stage(0); stage(1);

    for(int t=0;t<NT_K;t++){
        cp_wait_tail((t+1<NT_K)?1:0);
        __syncthreads();
        const float* As = sm + (t&1)*STG;
        const float* Bs = As + ABUF;
#pragma unroll
        for(int kbk=0;kbk<4;kbk++){
            float4 avb[2], avs[2];
#pragma unroll
            for(int mf=0;mf<2;mf++){
                int r = mq*32 + mf*16 + (lane>>2);
                int c = kbk*8 + (lane&3);
                float4 av = make_float4(As[r*AST + c],     As[(r+8)*AST + c],
                                        As[r*AST + c + 4], As[(r+8)*AST + c + 4]);
                avb[mf] = make_float4(totf(av.x), totf(av.y), totf(av.z), totf(av.w));
                avs[mf] = make_float4(av.x-avb[mf].x, av.y-avb[mf].y,
                                      av.z-avb[mf].z, av.w-avb[mf].w);
            }
#pragma unroll
            for(int nf=0;nf<4;nf++){
                int bj = (kbk*8 + (lane&3))*BST + nq*32 + nf*8 + (lane>>2);
                float2 bv = make_float2(Bs[bj], Bs[bj + 4*BST]);
                float2 bvb = make_float2(totf(bv.x), totf(bv.y));
                float2 bvs = make_float2(bv.x-bvb.x, bv.y-bvb.y);
#pragma unroll
                for(int mf=0;mf<2;mf++){
                    mma8(acc[mf][nf], avb[mf], bvb);
                    mma8(acc[mf][nf], avb[mf], bvs);
                    mma8(acc[mf][nf], avs[mf], bvb);
                }
            }
        }
        __syncthreads();
        if(t+2 < NT_K) stage(t+2);
    }

    const int r0 = i0 + mq*32, c0 = n0 + nq*32;
#pragma unroll
    for(int mf=0;mf<2;mf++){
        int row = r0 + mf*16 + (lane>>2);
        size_t o0 = (size_t)row*256 + c0 + (lane&3)*2;
        size_t o1 = o0 + (size_t)8*256;
#pragma unroll
        for(int nf=0;nf<4;nf++){
            *(float2*)(g_WhR + o0 + nf*8) =
                make_float2(totf(acc[mf][nf][0]), totf(acc[mf][nf][1]));
            *(float2*)(g_WhR + o1 + nf*8) =
                make_float2(totf(acc[mf][nf][2]), totf(acc[mf][nf][3]));
        }
    }
}

// ---------------------------------------------------------------------------
// fatB (R15-verified): bid<512 -> GEMM (recompute alpha); else alpha writer.
// ---------------------------------------------------------------------------
__global__ __launch_bounds__(128,5)
void gat_fused(float* __restrict__ h_out, float* __restrict__ alpha_out){
    extern __shared__ float sm[];
    const int tid=threadIdx.x, lane=tid&31, wid=tid>>5;
    const int bid = blockIdx.x;

    if(bid < 512){
        const int it=bid&31, bh=bid>>5, b=bh>>2, h=bh&3;
        const int i0=it*64;
        const float* wbase = g_WhR + (size_t)b*Nn*Dd + h*64;
        const float* uvbase = (const float*)(g_uv + (size_t)bh*Nn);
        const uint32_t* bitbase = g_bits + (size_t)b*64*Nn;

        const int r_lo = wid*16 + (lane>>2);
        const int gi = i0 + r_lo;
        float2 pq0 = g_pq[(size_t)bh*Nn + gi];
        float2 pq1 = g_pq[(size_t)bh*Nn + gi + 8];
        const float iv0 = g_ivs[(size_t)bh*Nn + gi];
        const float iv1 = g_ivs[(size_t)bh*Nn + gi + 8];
        const float P0 = pq0.x*iv0, Q0 = pq0.y*iv0;
        const float P1 = pq1.x*iv1, Q1 = pq1.y*iv1;

        float acc[8][4];
#pragma unroll
        for(int nf=0;nf<8;nf++)
#pragma unroll
            for(int q=0;q<4;q++) acc[nf][q]=0.f;

        auto stage=[&](int t){
            float* S = sm + (t&3)*STG3F;
            const int row = tid>>4, ch = tid&15;
#pragma unroll
            for(int k=0;k<4;k++)
                cpasync16(S + (row+k*8)*BST + ch*4,
                          wbase + (size_t)(t*32+row+k*8)*Dd + ch*4);
            if(tid<16) cpasync16(S + UV_OFF + tid*4, uvbase + t*64 + tid*4);
            else if(tid<32) cpasync16(S + BIT_OFF + (tid-16)*4,
                             (const float*)(bitbase + (size_t)t*Nn + i0) + (tid-16)*4);
            CP_COMMIT();
        };

        stage(0); stage(1); stage(2);

        for(int t=0;t<NT;t++){
            cp_wait_tail(NT-1-t);
            __syncthreads();
            if(t+3 < NT) stage(t+3);
            const float* S = sm + (t&3)*STG3F;
            const float2* uvt = (const float2*)(S + UV_OFF);
            const uint32_t* bw = (const uint32_t*)(S + BIT_OFF);
            const uint32_t b0 = bw[r_lo], b1 = bw[r_lo+8];
#pragma unroll
            for(int kb=0;kb<4;kb++){
                const int c0 = kb*8 + (lane&3);
                float2 x0 = uvt[c0];
                float2 x1 = uvt[c0+4];
                float ax = ((b0>>c0)&1u)     ? fmaxf(P0*x0.x, Q0*x0.y) : 0.f;
                float ay = ((b1>>c0)&1u)     ? fmaxf(P1*x0.x, Q1*x0.y) : 0.f;
                float az = ((b0>>(c0+4))&1u) ? fmaxf(P0*x1.x, Q0*x1.y) : 0.f;
                float aw = ((b1>>(c0+4))&1u) ? fmaxf(P1*x1.x, Q1*x1.y) : 0.f;
                float4 av = make_float4(ax,ay,az,aw);
#pragma unroll
                for(int nf=0;nf<8;nf++){
                    int bj = c0*BST + nf*8 + (lane>>2);
                    float2 bv = make_float2(S[bj], S[bj + 4*BST]);
                    mma8(acc[nf], av, bv);
                }
            }
        }

        const int row = i0 + r_lo;
        float* p0 = h_out + ((size_t)(b*Nn)+row)*Dd + h*64 + (lane&3)*2;
        float* p1 = p0 + (size_t)8*Dd;
#pragma unroll
        for(int nf=0;nf<8;nf++){
            *(float2*)(p0+nf*8) = make_float2(acc[nf][0],acc[nf][1]);
            *(float2*)(p1+nf*8) = make_float2(acc[nf][2],acc[nf][3]);
        }
    } else {
        const int wb = bid - 512;
        const int b  = wb >> 8;
        const int i0 = (wb & 255) * 8;
        float* sp  = sm;
        float* sq  = sm + 32;
        float* siv = sm + 64;
        uint32_t* sbw = (uint32_t*)(sm + 96);

        if(tid<32){
            int g = (b*Hh + (tid>>3))*Nn + i0 + (tid&7);
            float2 pq = g_pq[g];
            sp[tid]=pq.x; sq[tid]=pq.y; siv[tid]=g_ivs[g];
        }
#pragma unroll
        for(int k=0;k<4;k++){
            int item = tid + k*128;
            int w = item>>3, i = item&7;
            sbw[i*64+w] = g_bits[((size_t)b*64 + w)*Nn + i0 + i];
        }
        __syncthreads();

        const int h = tid>>5, c = tid&31;
        const float* uvh = (const float*)(g_uv + (size_t)(b*Hh+h)*Nn);
        float* ab = alpha_out + ((size_t)((b*Hh+h)*Nn) + i0)*Nn;
        float PP[8], QQ[8];
#pragma unroll
        for(int i=0;i<8;i++){
            PP[i] = sp[h*8+i]*siv[h*8+i];
            QQ[i] = sq[h*8+i]*siv[h*8+i];
        }
#pragma unroll 2
        for(int jc=0;jc<16;jc++){
            const int j = jc*128 + c*4;
            float4 x0 = *(const float4*)(uvh + 2*j);
            float4 x1 = *(const float4*)(uvh + 2*j + 4);
            const int w  = j>>5;
            const int sh = ((j>>2)&7)*4;
#pragma unroll
            for(int i=0;i<8;i++){
                uint32_t nib = sbw[i*64+w] >> sh;
                float4 o;
                o.x = (nib&1u) ? fmaxf(PP[i]*x0.x, QQ[i]*x0.y) : 0.f;
                o.y = (nib&2u) ? fmaxf(PP[i]*x0.z, QQ[i]*x0.w) : 0.f;
                o.z = (nib&4u) ? fmaxf(PP[i]*x1.x, QQ[i]*x1.y) : 0.f;
                o.w = (nib&8u) ? fmaxf(PP[i]*x1.z, QQ[i]*x1.w) : 0.f;
                *(float4*)(ab + (size_t)i*Nn + j) = o;
            }
        }
    }
}

// ---------------------------------------------------------------------------
extern "C" void kernel_launch(void* const* d_in, const int* in_sizes, int n_in,
                              void* d_out, int out_size){
    const float* h     = (const float*)d_in[0];
    const int*   adj   = (const int*)d_in[1];
    const float* W     = (const float*)d_in[2];
    const float* a_src = (const float*)d_in[3];
    const float* a_dst = (const float*)d_in[4];
    float* out = (float*)d_out;

    const long long houtN  = (long long)Bc*Nn*Dd;
    const long long alphaN = (long long)Bc*Hh*Nn*Nn;
    bool has_alpha = ((long long)out_size >= houtN + alphaN);
    float* alpha_buf;
    if(has_alpha){
        alpha_buf = out + houtN;
    } else {
        cudaGetSymbolAddress((void**)&alpha_buf, g_alpha_s);
    }

    cudaFuncSetAttribute(gat_fatA, cudaFuncAttributeMaxDynamicSharedMemorySize,
                         SMEM_A2);
    cudaFuncSetAttribute(gat_fused, cudaFuncAttributeMaxDynamicSharedMemorySize,
                         SMEM_G);

    gat_wa<<<1,256>>>(W, a_src, a_dst);
    gat_proj<<<(Bc*Nn)/8,256>>>(h);
    gat_fatA<<<1024+256,256,SMEM_A2>>>(adj, h, W);
    gat_fused<<<512+1024,128,SMEM_G>>>(out, alpha_buf);
}